// round 9
// baseline (speedup 1.0000x reference)
#include <cuda_runtime.h>
#include <cuda_fp16.h>
#include <cstdint>
#include <cstddef>

#define N_ROWS     131072
#define D_IN       512
#define D_H        1024
#define D_OUT      128
#define NUM_GROUPS 1024
#define LN_EPS     1e-5f

// ---------------- scratch (device globals: allocation-free rule) -------------
__device__ __half g_bufA[(size_t)N_ROWS * 2048];      // hi|lo fp16 expanded A
__device__ float  g_h  [(size_t)N_ROWS * D_H];        // fp32 hidden
__device__ float  g_mean[(size_t)NUM_GROUPS * D_H];   // 4 MB group means
__device__ __half g_Bt1[(size_t)D_H * D_IN];          // W1^T fp16 [1024, 512]
__device__ __half g_Bt2[(size_t)D_H * D_H];           // W2^T fp16 [1024, 1024]

// ======================= helpers ============================================
__device__ __forceinline__ uint32_t smem_u32(const void* p) {
    uint32_t a;
    asm("{ .reg .u64 t; cvta.to.shared.u64 t, %1; cvt.u32.u64 %0, t; }" : "=r"(a) : "l"(p));
    return a;
}
__device__ __forceinline__ uint32_t sw128(uint32_t b) { return b ^ ((b >> 3) & 0x70); }
__device__ __forceinline__ void cp_async16(uint32_t dst, const void* src) {
    asm volatile("cp.async.cg.shared.global [%0], [%1], 16;" :: "r"(dst), "l"(src) : "memory");
}
__device__ __forceinline__ void ldsm_x4(uint32_t* r, uint32_t addr) {
    asm volatile("ldmatrix.sync.aligned.m8n8.x4.shared.b16 {%0,%1,%2,%3}, [%4];"
                 : "=r"(r[0]), "=r"(r[1]), "=r"(r[2]), "=r"(r[3]) : "r"(addr));
}
__device__ __forceinline__ void mma_f16(float* c, const uint32_t* a, uint32_t b0, uint32_t b1) {
    asm volatile(
        "mma.sync.aligned.m16n8k16.row.col.f32.f16.f16.f32 "
        "{%0,%1,%2,%3}, {%4,%5,%6,%7}, {%8,%9}, {%0,%1,%2,%3};"
        : "+f"(c[0]), "+f"(c[1]), "+f"(c[2]), "+f"(c[3])
        : "r"(a[0]), "r"(a[1]), "r"(a[2]), "r"(a[3]), "r"(b0), "r"(b1));
}

// ======================= mma.sync 2-term fp16 GEMM ==========================
// C[M, Ncols] = relu(A2 @ B2^T + bias);
// A2 = [M, 2K] fp16 (hi|lo regions), B logical [N, 2K] = (Bh | Bh) realized by
// re-reading Bt [N, K] fp16 for the second K block. k' in [0, 2K).
// CTA tile 128x256, 8 warps in 2(m) x 4(n), warp tile 64x64.
#define BM 128
#define BN 256
#define BK 64
#define STAGES 4
#define A_BYTES (BM * 128)                  // 16 KB
#define B_BYTES (BN * 128)                  // 32 KB
#define STAGE_BYTES (A_BYTES + B_BYTES)     // 48 KB

__global__ void __launch_bounds__(256, 1)
gemm_mma(const __half* __restrict__ A, const __half* __restrict__ Bt,
         const float* __restrict__ bias, float* __restrict__ C,
         int K, int Ncols, int do_relu)
{
    extern __shared__ __align__(1024) char smem[];
    const uint32_t sbase = smem_u32(smem);
    const int tid = threadIdx.x, lane = tid & 31, wid = tid >> 5;
    const int wm = wid & 1, wn = wid >> 1;                 // 2 x 4 warp grid
    const int m0 = blockIdx.y * BM, n0 = blockIdx.x * BN;
    const int lda = 2 * K;
    const int NC = (2 * K) / BK;

    auto fill = [&](int ci, int s) {
        const int kp = ci * BK;                       // A column (hi|lo over 2K)
        const int kb = (kp < K) ? kp : (kp - K);      // B column (reuse Bh)
        const uint32_t sA = sbase + s * STAGE_BYTES;
        const uint32_t sB = sA + A_BYTES;
#pragma unroll
        for (int j = 0; j < 4; j++) {                 // A: 1024 x 16B
            const int c = tid + j * 256;
            const int r = c >> 3, col = (c & 7) * 16;
            cp_async16(sA + sw128(r * 128 + col),
                       (const char*)(A + (size_t)(m0 + r) * lda + kp) + col);
        }
#pragma unroll
        for (int j = 0; j < 8; j++) {                 // B: 2048 x 16B
            const int c = tid + j * 256;
            const int r = c >> 3, col = (c & 7) * 16;
            cp_async16(sB + sw128(r * 128 + col),
                       (const char*)(Bt + (size_t)(n0 + r) * K + kb) + col);
        }
        asm volatile("cp.async.commit_group;" ::: "memory");
    };

    float acc[4][8][4];
#pragma unroll
    for (int i = 0; i < 4; i++)
#pragma unroll
        for (int j = 0; j < 8; j++)
#pragma unroll
            for (int r = 0; r < 4; r++) acc[i][j][r] = 0.f;

    // prologue: fill ALL stages (STAGES-1 chunks of lookahead beyond current)
    for (int j = 0; j < STAGES && j < NC; j++) fill(j, j);

    for (int i = 0; i < NC; i++) {
        const int s = i % STAGES;
        asm volatile("cp.async.wait_group %0;" :: "n"(STAGES - 1) : "memory");
        __syncthreads();
        const uint32_t sA = sbase + s * STAGE_BYTES;
        const uint32_t sB = sA + A_BYTES;

#pragma unroll
        for (int k16 = 0; k16 < BK / 16; k16++) {
            const uint32_t kb = k16 * 32 + (lane >> 4) * 16;
            uint32_t a[4][4];
#pragma unroll
            for (int mt = 0; mt < 4; mt++) {
                const int r = wm * 64 + mt * 16 + (lane & 15);
                ldsm_x4(a[mt], sA + sw128(r * 128 + kb));
            }
            uint32_t b[4][4];
#pragma unroll
            for (int nt2 = 0; nt2 < 4; nt2++) {
                const int r = wn * 64 + nt2 * 16 + (lane & 15);
                ldsm_x4(b[nt2], sB + sw128(r * 128 + kb));
            }
#pragma unroll
            for (int mt = 0; mt < 4; mt++)
#pragma unroll
                for (int nt = 0; nt < 8; nt++)
                    mma_f16(acc[mt][nt], a[mt], b[nt >> 1][nt & 1], b[nt >> 1][2 + (nt & 1)]);
        }
        __syncthreads();
        if (i + STAGES < NC) fill(i + STAGES, s);
    }

    // epilogue: bias + relu, fp32 stores
#pragma unroll
    for (int mt = 0; mt < 4; mt++) {
#pragma unroll
        for (int nt = 0; nt < 8; nt++) {
            const int col = n0 + wn * 64 + nt * 8 + (lane & 3) * 2;
            const float b0 = bias[col], b1 = bias[col + 1];
            const int r0 = m0 + wm * 64 + mt * 16 + (lane >> 2);
            float v0 = acc[mt][nt][0] + b0, v1 = acc[mt][nt][1] + b1;
            float v2 = acc[mt][nt][2] + b0, v3 = acc[mt][nt][3] + b1;
            if (do_relu) {
                v0 = fmaxf(v0, 0.f); v1 = fmaxf(v1, 0.f);
                v2 = fmaxf(v2, 0.f); v3 = fmaxf(v3, 0.f);
            }
            *(float2*)(C + (size_t)r0 * Ncols + col)       = make_float2(v0, v1);
            *(float2*)(C + (size_t)(r0 + 8) * Ncols + col) = make_float2(v2, v3);
        }
    }
}

// =================== operand prep kernels ===================================
__device__ __forceinline__ void split_f16(float x, __half& hi, __half& lo) {
    hi = __float2half_rn(x);
    lo = __float2half_rn(x - __half2float(hi));
}

// X [N, 512] f32 -> bufA [N, 1024] fp16 (hi | lo)
__global__ void __launch_bounds__(256)
convertX(const float* __restrict__ X, __half* __restrict__ out)
{
    const size_t i4 = ((size_t)blockIdx.x * 256 + threadIdx.x) * 4;
    if (i4 >= (size_t)N_ROWS * D_IN) return;
    const size_t r = i4 / D_IN, c = i4 % D_IN;
    float4 v = *(const float4*)(X + i4);
    __half h[4], l[4];
    split_f16(v.x, h[0], l[0]); split_f16(v.y, h[1], l[1]);
    split_f16(v.z, h[2], l[2]); split_f16(v.w, h[3], l[3]);
    __half* oh = out + r * 1024 + c;
    __half* ol = out + r * 1024 + D_IN + c;
    *(__half2*)(oh)     = __halves2half2(h[0], h[1]);
    *(__half2*)(oh + 2) = __halves2half2(h[2], h[3]);
    *(__half2*)(ol)     = __halves2half2(l[0], l[1]);
    *(__half2*)(ol + 2) = __halves2half2(l[2], l[3]);
}

// W [K, Ncols] f32 -> Bt [Ncols, K] fp16 (rounded)
__global__ void __launch_bounds__(256)
convertW(const float* __restrict__ W, __half* __restrict__ Bt, int K, int Ncols)
{
    const size_t i = (size_t)blockIdx.x * 256 + threadIdx.x;
    if (i >= (size_t)K * Ncols) return;
    const int n = (int)(i % Ncols), k = (int)(i / Ncols);
    Bt[(size_t)n * K + k] = __float2half_rn(W[(size_t)k * Ncols + n]);
}

// -------- shared LN row-stat helper (256 threads, 1024 elems) ---------------
__device__ __forceinline__ void ln_stats(float4 v, float& mu, float& rs) {
    float s = v.x + v.y + v.z + v.w;
    float ss = v.x * v.x + v.y * v.y + v.z * v.z + v.w * v.w;
#pragma unroll
    for (int o = 16; o > 0; o >>= 1) {
        s  += __shfl_xor_sync(0xFFFFFFFFu, s,  o);
        ss += __shfl_xor_sync(0xFFFFFFFFu, ss, o);
    }
    __shared__ float ws[8], wss[8];
    const int t = threadIdx.x, w = t >> 5, l = t & 31;
    if (l == 0) { ws[w] = s; wss[w] = ss; }
    __syncthreads();
    if (w == 0) {
        s  = (l < 8) ? ws[l]  : 0.f;
        ss = (l < 8) ? wss[l] : 0.f;
#pragma unroll
        for (int o = 4; o > 0; o >>= 1) {
            s  += __shfl_xor_sync(0xFFFFFFFFu, s,  o);
            ss += __shfl_xor_sync(0xFFFFFFFFu, ss, o);
        }
        if (l == 0) { ws[0] = s; wss[0] = ss; }
    }
    __syncthreads();
    const float inv = 1.f / (float)D_H;
    mu = ws[0] * inv;
    const float var = fmaxf(wss[0] * inv - mu * mu, 0.f);
    rs = rsqrtf(var + LN_EPS);
}

// LayerNorm(h fp32 [N,1024]) -> bufA [N, 2048] fp16 (hi | lo)
__global__ void __launch_bounds__(256)
ln_convert(const float* __restrict__ H, const float* __restrict__ gamma,
           const float* __restrict__ beta, __half* __restrict__ out)
{
    const int row = blockIdx.x;
    const int t = threadIdx.x;
    float4 v = *(const float4*)(H + (size_t)row * D_H + t * 4);
    float mu, rs;
    ln_stats(v, mu, rs);

    float4 gv = *(const float4*)(gamma + t * 4);
    float4 bv = *(const float4*)(beta  + t * 4);
    float n0 = (v.x - mu) * rs * gv.x + bv.x;
    float n1 = (v.y - mu) * rs * gv.y + bv.y;
    float n2 = (v.z - mu) * rs * gv.z + bv.z;
    float n3 = (v.w - mu) * rs * gv.w + bv.w;
    __half h[4], lo[4];
    split_f16(n0, h[0], lo[0]); split_f16(n1, h[1], lo[1]);
    split_f16(n2, h[2], lo[2]); split_f16(n3, h[3], lo[3]);
    __half* oh = out + (size_t)row * 2048 + t * 4;
    __half* ol = oh + D_H;
    *(__half2*)(oh)     = __halves2half2(h[0], h[1]);
    *(__half2*)(oh + 2) = __halves2half2(h[2], h[3]);
    *(__half2*)(ol)     = __halves2half2(lo[0], lo[1]);
    *(__half2*)(ol + 2) = __halves2half2(lo[2], lo[3]);
}

// ======= fused LayerNorm + deterministic segment mean =======================
#define SEG_CAP 4096
__global__ void __launch_bounds__(128)
segmean_ln(const float* __restrict__ H, const int* __restrict__ batch,
           const float* __restrict__ gamma, const float* __restrict__ beta,
           float* __restrict__ mean)
{
    const int g = blockIdx.x;
    const int t = threadIdx.x;
    const int w = t >> 5, l = t & 31;

    __shared__ int s_cnt[128];
    __shared__ int s_idx[SEG_CAP];
    __shared__ int s_total;
    __shared__ float s_red[2][8];   // [parity][ws0..3 | wss0..3]

    int cnt = 0;
    for (int i = t; i < N_ROWS; i += 128)
        cnt += (batch[i] == g) ? 1 : 0;
    s_cnt[t] = cnt;
    __syncthreads();

    int off = 0;
    for (int u = 0; u < t; u++) off += s_cnt[u];
    if (t == 127) s_total = off + cnt;
    __syncthreads();
    const int total = s_total;

    int o = off;
    for (int i = t; i < N_ROWS; i += 128) {
        if (batch[i] == g) {
            if (o < SEG_CAP) s_idx[o] = i;
            o++;
        }
    }
    __syncthreads();

    float4 gv0 = *(const float4*)(gamma + t * 8);
    float4 gv1 = *(const float4*)(gamma + t * 8 + 4);
    float4 bv0 = *(const float4*)(beta  + t * 8);
    float4 bv1 = *(const float4*)(beta  + t * 8 + 4);

    float acc[8];
#pragma unroll
    for (int c = 0; c < 8; c++) acc[c] = 0.f;

    const int m = total < SEG_CAP ? total : SEG_CAP;
    const float invD = 1.f / (float)D_H;
    for (int j = 0; j < m; j++) {
        const float* row = H + (size_t)s_idx[j] * D_H + t * 8;
        float4 a = *(const float4*)(row);
        float4 b = *(const float4*)(row + 4);
        float s  = a.x + a.y + a.z + a.w + b.x + b.y + b.z + b.w;
        float ss = a.x * a.x + a.y * a.y + a.z * a.z + a.w * a.w
                 + b.x * b.x + b.y * b.y + b.z * b.z + b.w * b.w;
#pragma unroll
        for (int od = 16; od > 0; od >>= 1) {
            s  += __shfl_xor_sync(0xFFFFFFFFu, s,  od);
            ss += __shfl_xor_sync(0xFFFFFFFFu, ss, od);
        }
        const int p = j & 1;
        if (l == 0) { s_red[p][w] = s; s_red[p][4 + w] = ss; }
        __syncthreads();
        const float S  = s_red[p][0] + s_red[p][1] + s_red[p][2] + s_red[p][3];
        const float SS = s_red[p][4] + s_red[p][5] + s_red[p][6] + s_red[p][7];
        const float mu = S * invD;
        const float var = fmaxf(SS * invD - mu * mu, 0.f);
        const float rs = rsqrtf(var + LN_EPS);
        acc[0] += (a.x - mu) * rs * gv0.x + bv0.x;
        acc[1] += (a.y - mu) * rs * gv0.y + bv0.y;
        acc[2] += (a.z - mu) * rs * gv0.z + bv0.z;
        acc[3] += (a.w - mu) * rs * gv0.w + bv0.w;
        acc[4] += (b.x - mu) * rs * gv1.x + bv1.x;
        acc[5] += (b.y - mu) * rs * gv1.y + bv1.y;
        acc[6] += (b.z - mu) * rs * gv1.z + bv1.z;
        acc[7] += (b.w - mu) * rs * gv1.w + bv1.w;
    }

    const float inv = (total > 0) ? 1.f / (float)total : 0.f;
    float* dst = mean + (size_t)g * D_H + t * 8;
#pragma unroll
    for (int c = 0; c < 8; c += 4)
        *(float4*)(dst + c) = make_float4(acc[c] * inv, acc[c + 1] * inv,
                                          acc[c + 2] * inv, acc[c + 3] * inv);
}

// --------- tiny fp32 GEMM: out[G,128] = mean[G,1024] @ W3[1024,128] + b3 ----
__global__ void __launch_bounds__(128)
minigemm(const float* __restrict__ mean, const float* __restrict__ W3,
         const float* __restrict__ b3, float* __restrict__ out)
{
    __shared__ float sm[8][D_H];            // 8 group rows, 32 KB
    const int g0 = blockIdx.x * 8;
    const int t = threadIdx.x;              // output column

    for (int i = t; i < 8 * D_H; i += 128)
        sm[i >> 10][i & 1023] = mean[(size_t)(g0 + (i >> 10)) * D_H + (i & 1023)];
    __syncthreads();

    float acc[8];
#pragma unroll
    for (int r = 0; r < 8; r++) acc[r] = 0.f;
    for (int k = 0; k < D_H; k++) {
        const float w = W3[(size_t)k * D_OUT + t];
#pragma unroll
        for (int r = 0; r < 8; r++) acc[r] += sm[r][k] * w;
    }
    const float bb = b3[t];
#pragma unroll
    for (int r = 0; r < 8; r++)
        out[(size_t)(g0 + r) * D_OUT + t] = acc[r] + bb;
}

// ---------------- launch -----------------------------------------------------
extern "C" void kernel_launch(void* const* d_in, const int* in_sizes, int n_in,
                              void* d_out, int out_size)
{
    const float* X   = (const float*)d_in[0];
    const float* W1  = (const float*)d_in[1];
    const float* b1  = (const float*)d_in[2];
    const float* g1  = (const float*)d_in[3];
    const float* be1 = (const float*)d_in[4];
    const float* W2  = (const float*)d_in[5];
    const float* b2  = (const float*)d_in[6];
    const float* g2  = (const float*)d_in[7];
    const float* be2 = (const float*)d_in[8];
    const float* W3  = (const float*)d_in[9];
    const float* b3  = (const float*)d_in[10];
    const int*   ab  = (const int*)d_in[11];
    float* out = (float*)d_out;

    __half *bufA, *Bt1, *Bt2;
    float *h, *mean;
    cudaGetSymbolAddress((void**)&bufA, g_bufA);
    cudaGetSymbolAddress((void**)&h,    g_h);
    cudaGetSymbolAddress((void**)&mean, g_mean);
    cudaGetSymbolAddress((void**)&Bt1,  g_Bt1);
    cudaGetSymbolAddress((void**)&Bt2,  g_Bt2);

    const int SMEM = STAGES * STAGE_BYTES;   // 192 KB
    static bool attr_set = false;
    if (!attr_set) {
        cudaFuncSetAttribute(gemm_mma, cudaFuncAttributeMaxDynamicSharedMemorySize, SMEM);
        attr_set = true;
    }

    // operand prep
    convertW<<<(D_IN * D_H + 255) / 256, 256>>>(W1, Bt1, D_IN, D_H);
    convertW<<<(D_H * D_H + 255) / 256, 256>>>(W2, Bt2, D_H, D_H);
    convertX<<<(int)(((size_t)N_ROWS * D_IN / 4 + 255) / 256), 256>>>(X, bufA);

    // layer 1: [N,512] @ [512,1024] -> h   (2-term fp16 split: 2K expansion)
    gemm_mma<<<dim3(D_H / BN, N_ROWS / BM), 256, SMEM>>>(
        bufA, Bt1, b1, h, D_IN, D_H, 1);
    ln_convert<<<N_ROWS, 256>>>(h, g1, be1, bufA);

    // layer 2: [N,1024] @ [1024,1024] -> h (raw, pre-LN)
    gemm_mma<<<dim3(D_H / BN, N_ROWS / BM), 256, SMEM>>>(
        bufA, Bt2, b2, h, D_H, D_H, 1);

    // fused LN2 + per-group mean, then tiny fp32 GEMM (layer 3 via linearity)
    segmean_ln<<<NUM_GROUPS, 128>>>(h, ab, g2, be2, mean);
    minigemm<<<NUM_GROUPS / 8, 128>>>(mean, W3, b3, out);
}

// round 10
// speedup vs baseline: 1.0530x; 1.0530x over previous
#include <cuda_runtime.h>
#include <cuda_fp16.h>
#include <cstdint>
#include <cstddef>

#define N_ROWS     131072
#define D_IN       512
#define D_H        1024
#define D_OUT      128
#define NUM_GROUPS 1024
#define LN_EPS     1e-5f

// ---------------- scratch (device globals: allocation-free rule) -------------
__device__ __half g_bufA[(size_t)N_ROWS * 2048];      // hi|lo fp16 expanded A
__device__ float  g_h  [(size_t)N_ROWS * D_H];        // fp32 hidden
__device__ float  g_mean[(size_t)NUM_GROUPS * D_H];   // 4 MB group means
__device__ __half g_Bt1[(size_t)D_H * D_IN];          // W1^T fp16 [1024, 512]
__device__ __half g_Bt2[(size_t)D_H * D_H];           // W2^T fp16 [1024, 1024]

// ======================= helpers ============================================
__device__ __forceinline__ uint32_t smem_u32(const void* p) {
    uint32_t a;
    asm("{ .reg .u64 t; cvta.to.shared.u64 t, %1; cvt.u32.u64 %0, t; }" : "=r"(a) : "l"(p));
    return a;
}
__device__ __forceinline__ uint32_t sw128(uint32_t b) { return b ^ ((b >> 3) & 0x70); }
__device__ __forceinline__ void cp_async16(uint32_t dst, const void* src) {
    asm volatile("cp.async.cg.shared.global [%0], [%1], 16;" :: "r"(dst), "l"(src) : "memory");
}
__device__ __forceinline__ void ldsm_x4(uint32_t* r, uint32_t addr) {
    asm volatile("ldmatrix.sync.aligned.m8n8.x4.shared.b16 {%0,%1,%2,%3}, [%4];"
                 : "=r"(r[0]), "=r"(r[1]), "=r"(r[2]), "=r"(r[3]) : "r"(addr));
}
__device__ __forceinline__ void mma_f16(float* c, const uint32_t* a, uint32_t b0, uint32_t b1) {
    asm volatile(
        "mma.sync.aligned.m16n8k16.row.col.f32.f16.f16.f32 "
        "{%0,%1,%2,%3}, {%4,%5,%6,%7}, {%8,%9}, {%0,%1,%2,%3};"
        : "+f"(c[0]), "+f"(c[1]), "+f"(c[2]), "+f"(c[3])
        : "r"(a[0]), "r"(a[1]), "r"(a[2]), "r"(a[3]), "r"(b0), "r"(b1));
}

// ======================= mma.sync 2-term fp16 GEMM ==========================
// C[M, Ncols] = relu((A_hi + A_lo) @ Bt^T + bias);
// A2 = [M, 2K] fp16 (hi cols [0,K), lo cols [K,2K)), Bt = [N, K] fp16.
// Stage = [A_hi 16KB | A_lo 16KB | B 16KB] over a BK=64 k-chunk; both split
// terms are computed per B fragment into the same accumulators (A-frag regs
// reused), giving 8 LDSM per 32 HMMA at 128 regs / 2 CTAs per SM.
#define BM 128
#define BN 128
#define BK 64
#define STAGES 2
#define R_BYTES (BM * 128)                  // 16 KB per region
#define STAGE_BYTES (3 * R_BYTES)           // 48 KB

__global__ void __launch_bounds__(256, 2)
gemm_mma(const __half* __restrict__ A, const __half* __restrict__ Bt,
         const float* __restrict__ bias, float* __restrict__ C,
         int K, int Ncols, int do_relu)
{
    extern __shared__ __align__(1024) char smem[];
    const uint32_t sbase = smem_u32(smem);
    const int tid = threadIdx.x, lane = tid & 31, wid = tid >> 5;
    const int wm = wid & 3, wn = wid >> 2;                 // 4 x 2 warp grid
    const int m0 = blockIdx.y * BM, n0 = blockIdx.x * BN;
    const int lda = 2 * K;
    const int NC = K / BK;

    auto fill = [&](int ci, int s) {
        const int kp = ci * BK;
        const uint32_t sAh = sbase + s * STAGE_BYTES;
        const uint32_t sAl = sAh + R_BYTES;
        const uint32_t sB  = sAh + 2 * R_BYTES;
#pragma unroll
        for (int j = 0; j < 4; j++) {                 // A hi
            const int c = tid + j * 256;
            const int r = c >> 3, col = (c & 7) * 16;
            cp_async16(sAh + sw128(r * 128 + col),
                       (const char*)(A + (size_t)(m0 + r) * lda + kp) + col);
        }
#pragma unroll
        for (int j = 0; j < 4; j++) {                 // A lo
            const int c = tid + j * 256;
            const int r = c >> 3, col = (c & 7) * 16;
            cp_async16(sAl + sw128(r * 128 + col),
                       (const char*)(A + (size_t)(m0 + r) * lda + K + kp) + col);
        }
#pragma unroll
        for (int j = 0; j < 4; j++) {                 // B
            const int c = tid + j * 256;
            const int r = c >> 3, col = (c & 7) * 16;
            cp_async16(sB + sw128(r * 128 + col),
                       (const char*)(Bt + (size_t)(n0 + r) * K + kp) + col);
        }
        asm volatile("cp.async.commit_group;" ::: "memory");
    };

    float acc[2][8][4];
#pragma unroll
    for (int i = 0; i < 2; i++)
#pragma unroll
        for (int j = 0; j < 8; j++)
#pragma unroll
            for (int r = 0; r < 4; r++) acc[i][j][r] = 0.f;

    // prologue: fill both stages (1 chunk of lookahead beyond current)
    fill(0, 0);
    fill(1, 1);

    for (int i = 0; i < NC; i++) {
        const int s = i & 1;
        asm volatile("cp.async.wait_group %0;" :: "n"(1) : "memory");
        __syncthreads();
        const uint32_t sAh = sbase + s * STAGE_BYTES;
        const uint32_t sAl = sAh + R_BYTES;
        const uint32_t sB  = sAh + 2 * R_BYTES;

#pragma unroll
        for (int k16 = 0; k16 < BK / 16; k16++) {
            const uint32_t kb = k16 * 32 + (lane >> 4) * 16;
            uint32_t b[4][4];
#pragma unroll
            for (int nt2 = 0; nt2 < 4; nt2++) {
                const int r = wn * 64 + nt2 * 16 + (lane & 15);
                ldsm_x4(b[nt2], sB + sw128(r * 128 + kb));
            }
            uint32_t a[2][4];
#pragma unroll
            for (int mt = 0; mt < 2; mt++) {          // hi term
                const int r = wm * 32 + mt * 16 + (lane & 15);
                ldsm_x4(a[mt], sAh + sw128(r * 128 + kb));
            }
#pragma unroll
            for (int mt = 0; mt < 2; mt++)
#pragma unroll
                for (int nt = 0; nt < 8; nt++)
                    mma_f16(acc[mt][nt], a[mt], b[nt >> 1][nt & 1], b[nt >> 1][2 + (nt & 1)]);
#pragma unroll
            for (int mt = 0; mt < 2; mt++) {          // lo term (reuse a regs)
                const int r = wm * 32 + mt * 16 + (lane & 15);
                ldsm_x4(a[mt], sAl + sw128(r * 128 + kb));
            }
#pragma unroll
            for (int mt = 0; mt < 2; mt++)
#pragma unroll
                for (int nt = 0; nt < 8; nt++)
                    mma_f16(acc[mt][nt], a[mt], b[nt >> 1][nt & 1], b[nt >> 1][2 + (nt & 1)]);
        }
        __syncthreads();
        if (i + STAGES < NC) fill(i + STAGES, s);
        else asm volatile("cp.async.commit_group;" ::: "memory");
    }

    // epilogue: bias + relu, fp32 stores
#pragma unroll
    for (int mt = 0; mt < 2; mt++) {
#pragma unroll
        for (int nt = 0; nt < 8; nt++) {
            const int col = n0 + wn * 64 + nt * 8 + (lane & 3) * 2;
            const float b0 = bias[col], b1 = bias[col + 1];
            const int r0 = m0 + wm * 32 + mt * 16 + (lane >> 2);
            float v0 = acc[mt][nt][0] + b0, v1 = acc[mt][nt][1] + b1;
            float v2 = acc[mt][nt][2] + b0, v3 = acc[mt][nt][3] + b1;
            if (do_relu) {
                v0 = fmaxf(v0, 0.f); v1 = fmaxf(v1, 0.f);
                v2 = fmaxf(v2, 0.f); v3 = fmaxf(v3, 0.f);
            }
            *(float2*)(C + (size_t)r0 * Ncols + col)       = make_float2(v0, v1);
            *(float2*)(C + (size_t)(r0 + 8) * Ncols + col) = make_float2(v2, v3);
        }
    }
}

// =================== operand prep kernels ===================================
__device__ __forceinline__ void split_f16(float x, __half& hi, __half& lo) {
    hi = __float2half_rn(x);
    lo = __float2half_rn(x - __half2float(hi));
}

// X [N, 512] f32 -> bufA [N, 1024] fp16 (hi | lo)
__global__ void __launch_bounds__(256)
convertX(const float* __restrict__ X, __half* __restrict__ out)
{
    const size_t i4 = ((size_t)blockIdx.x * 256 + threadIdx.x) * 4;
    if (i4 >= (size_t)N_ROWS * D_IN) return;
    const size_t r = i4 / D_IN, c = i4 % D_IN;
    float4 v = *(const float4*)(X + i4);
    __half h[4], l[4];
    split_f16(v.x, h[0], l[0]); split_f16(v.y, h[1], l[1]);
    split_f16(v.z, h[2], l[2]); split_f16(v.w, h[3], l[3]);
    __half* oh = out + r * 1024 + c;
    __half* ol = out + r * 1024 + D_IN + c;
    *(__half2*)(oh)     = __halves2half2(h[0], h[1]);
    *(__half2*)(oh + 2) = __halves2half2(h[2], h[3]);
    *(__half2*)(ol)     = __halves2half2(l[0], l[1]);
    *(__half2*)(ol + 2) = __halves2half2(l[2], l[3]);
}

// W [K, Ncols] f32 -> Bt [Ncols, K] fp16 (rounded)
__global__ void __launch_bounds__(256)
convertW(const float* __restrict__ W, __half* __restrict__ Bt, int K, int Ncols)
{
    const size_t i = (size_t)blockIdx.x * 256 + threadIdx.x;
    if (i >= (size_t)K * Ncols) return;
    const int n = (int)(i % Ncols), k = (int)(i / Ncols);
    Bt[(size_t)n * K + k] = __float2half_rn(W[(size_t)k * Ncols + n]);
}

// -------- shared LN row-stat helper (256 threads, 1024 elems) ---------------
__device__ __forceinline__ void ln_stats(float4 v, float& mu, float& rs) {
    float s = v.x + v.y + v.z + v.w;
    float ss = v.x * v.x + v.y * v.y + v.z * v.z + v.w * v.w;
#pragma unroll
    for (int o = 16; o > 0; o >>= 1) {
        s  += __shfl_xor_sync(0xFFFFFFFFu, s,  o);
        ss += __shfl_xor_sync(0xFFFFFFFFu, ss, o);
    }
    __shared__ float ws[8], wss[8];
    const int t = threadIdx.x, w = t >> 5, l = t & 31;
    if (l == 0) { ws[w] = s; wss[w] = ss; }
    __syncthreads();
    if (w == 0) {
        s  = (l < 8) ? ws[l]  : 0.f;
        ss = (l < 8) ? wss[l] : 0.f;
#pragma unroll
        for (int o = 4; o > 0; o >>= 1) {
            s  += __shfl_xor_sync(0xFFFFFFFFu, s,  o);
            ss += __shfl_xor_sync(0xFFFFFFFFu, ss, o);
        }
        if (l == 0) { ws[0] = s; wss[0] = ss; }
    }
    __syncthreads();
    const float inv = 1.f / (float)D_H;
    mu = ws[0] * inv;
    const float var = fmaxf(wss[0] * inv - mu * mu, 0.f);
    rs = rsqrtf(var + LN_EPS);
}

// LayerNorm(h fp32 [N,1024]) -> bufA [N, 2048] fp16 (hi | lo)
__global__ void __launch_bounds__(256)
ln_convert(const float* __restrict__ H, const float* __restrict__ gamma,
           const float* __restrict__ beta, __half* __restrict__ out)
{
    const int row = blockIdx.x;
    const int t = threadIdx.x;
    float4 v = *(const float4*)(H + (size_t)row * D_H + t * 4);
    float mu, rs;
    ln_stats(v, mu, rs);

    float4 gv = *(const float4*)(gamma + t * 4);
    float4 bv = *(const float4*)(beta  + t * 4);
    float n0 = (v.x - mu) * rs * gv.x + bv.x;
    float n1 = (v.y - mu) * rs * gv.y + bv.y;
    float n2 = (v.z - mu) * rs * gv.z + bv.z;
    float n3 = (v.w - mu) * rs * gv.w + bv.w;
    __half h[4], lo[4];
    split_f16(n0, h[0], lo[0]); split_f16(n1, h[1], lo[1]);
    split_f16(n2, h[2], lo[2]); split_f16(n3, h[3], lo[3]);
    __half* oh = out + (size_t)row * 2048 + t * 4;
    __half* ol = oh + D_H;
    *(__half2*)(oh)     = __halves2half2(h[0], h[1]);
    *(__half2*)(oh + 2) = __halves2half2(h[2], h[3]);
    *(__half2*)(ol)     = __halves2half2(lo[0], lo[1]);
    *(__half2*)(ol + 2) = __halves2half2(lo[2], lo[3]);
}

// ======= fused LayerNorm + deterministic segment mean =======================
#define SEG_CAP 4096
__global__ void __launch_bounds__(128)
segmean_ln(const float* __restrict__ H, const int* __restrict__ batch,
           const float* __restrict__ gamma, const float* __restrict__ beta,
           float* __restrict__ mean)
{
    const int g = blockIdx.x;
    const int t = threadIdx.x;
    const int w = t >> 5, l = t & 31;

    __shared__ int s_cnt[128];
    __shared__ int s_idx[SEG_CAP];
    __shared__ int s_total;
    __shared__ float s_red[2][8];   // [parity][ws0..3 | wss0..3]

    int cnt = 0;
    for (int i = t; i < N_ROWS; i += 128)
        cnt += (batch[i] == g) ? 1 : 0;
    s_cnt[t] = cnt;
    __syncthreads();

    int off = 0;
    for (int u = 0; u < t; u++) off += s_cnt[u];
    if (t == 127) s_total = off + cnt;
    __syncthreads();
    const int total = s_total;

    int o = off;
    for (int i = t; i < N_ROWS; i += 128) {
        if (batch[i] == g) {
            if (o < SEG_CAP) s_idx[o] = i;
            o++;
        }
    }
    __syncthreads();

    float4 gv0 = *(const float4*)(gamma + t * 8);
    float4 gv1 = *(const float4*)(gamma + t * 8 + 4);
    float4 bv0 = *(const float4*)(beta  + t * 8);
    float4 bv1 = *(const float4*)(beta  + t * 8 + 4);

    float acc[8];
#pragma unroll
    for (int c = 0; c < 8; c++) acc[c] = 0.f;

    const int m = total < SEG_CAP ? total : SEG_CAP;
    const float invD = 1.f / (float)D_H;
    for (int j = 0; j < m; j++) {
        const float* row = H + (size_t)s_idx[j] * D_H + t * 8;
        float4 a = *(const float4*)(row);
        float4 b = *(const float4*)(row + 4);
        float s  = a.x + a.y + a.z + a.w + b.x + b.y + b.z + b.w;
        float ss = a.x * a.x + a.y * a.y + a.z * a.z + a.w * a.w
                 + b.x * b.x + b.y * b.y + b.z * b.z + b.w * b.w;
#pragma unroll
        for (int od = 16; od > 0; od >>= 1) {
            s  += __shfl_xor_sync(0xFFFFFFFFu, s,  od);
            ss += __shfl_xor_sync(0xFFFFFFFFu, ss, od);
        }
        const int p = j & 1;
        if (l == 0) { s_red[p][w] = s; s_red[p][4 + w] = ss; }
        __syncthreads();
        const float S  = s_red[p][0] + s_red[p][1] + s_red[p][2] + s_red[p][3];
        const float SS = s_red[p][4] + s_red[p][5] + s_red[p][6] + s_red[p][7];
        const float mu = S * invD;
        const float var = fmaxf(SS * invD - mu * mu, 0.f);
        const float rs = rsqrtf(var + LN_EPS);
        acc[0] += (a.x - mu) * rs * gv0.x + bv0.x;
        acc[1] += (a.y - mu) * rs * gv0.y + bv0.y;
        acc[2] += (a.z - mu) * rs * gv0.z + bv0.z;
        acc[3] += (a.w - mu) * rs * gv0.w + bv0.w;
        acc[4] += (b.x - mu) * rs * gv1.x + bv1.x;
        acc[5] += (b.y - mu) * rs * gv1.y + bv1.y;
        acc[6] += (b.z - mu) * rs * gv1.z + bv1.z;
        acc[7] += (b.w - mu) * rs * gv1.w + bv1.w;
    }

    const float inv = (total > 0) ? 1.f / (float)total : 0.f;
    float* dst = mean + (size_t)g * D_H + t * 8;
#pragma unroll
    for (int c = 0; c < 8; c += 4)
        *(float4*)(dst + c) = make_float4(acc[c] * inv, acc[c + 1] * inv,
                                          acc[c + 2] * inv, acc[c + 3] * inv);
}

// --------- tiny fp32 GEMM: out[G,128] = mean[G,1024] @ W3[1024,128] + b3 ----
__global__ void __launch_bounds__(128)
minigemm(const float* __restrict__ mean, const float* __restrict__ W3,
         const float* __restrict__ b3, float* __restrict__ out)
{
    __shared__ float sm[8][D_H];            // 8 group rows, 32 KB
    const int g0 = blockIdx.x * 8;
    const int t = threadIdx.x;              // output column

    for (int i = t; i < 8 * D_H; i += 128)
        sm[i >> 10][i & 1023] = mean[(size_t)(g0 + (i >> 10)) * D_H + (i & 1023)];
    __syncthreads();

    float acc[8];
#pragma unroll
    for (int r = 0; r < 8; r++) acc[r] = 0.f;
    for (int k = 0; k < D_H; k++) {
        const float w = W3[(size_t)k * D_OUT + t];
#pragma unroll
        for (int r = 0; r < 8; r++) acc[r] += sm[r][k] * w;
    }
    const float bb = b3[t];
#pragma unroll
    for (int r = 0; r < 8; r++)
        out[(size_t)(g0 + r) * D_OUT + t] = acc[r] + bb;
}

// ---------------- launch -----------------------------------------------------
extern "C" void kernel_launch(void* const* d_in, const int* in_sizes, int n_in,
                              void* d_out, int out_size)
{
    const float* X   = (const float*)d_in[0];
    const float* W1  = (const float*)d_in[1];
    const float* b1  = (const float*)d_in[2];
    const float* g1  = (const float*)d_in[3];
    const float* be1 = (const float*)d_in[4];
    const float* W2  = (const float*)d_in[5];
    const float* b2  = (const float*)d_in[6];
    const float* g2  = (const float*)d_in[7];
    const float* be2 = (const float*)d_in[8];
    const float* W3  = (const float*)d_in[9];
    const float* b3  = (const float*)d_in[10];
    const int*   ab  = (const int*)d_in[11];
    float* out = (float*)d_out;

    __half *bufA, *Bt1, *Bt2;
    float *h, *mean;
    cudaGetSymbolAddress((void**)&bufA, g_bufA);
    cudaGetSymbolAddress((void**)&h,    g_h);
    cudaGetSymbolAddress((void**)&mean, g_mean);
    cudaGetSymbolAddress((void**)&Bt1,  g_Bt1);
    cudaGetSymbolAddress((void**)&Bt2,  g_Bt2);

    const int SMEM = STAGES * STAGE_BYTES;   // 96 KB
    static bool attr_set = false;
    if (!attr_set) {
        cudaFuncSetAttribute(gemm_mma, cudaFuncAttributeMaxDynamicSharedMemorySize, SMEM);
        attr_set = true;
    }

    // operand prep
    convertW<<<(D_IN * D_H + 255) / 256, 256>>>(W1, Bt1, D_IN, D_H);
    convertW<<<(D_H * D_H + 255) / 256, 256>>>(W2, Bt2, D_H, D_H);
    convertX<<<(int)(((size_t)N_ROWS * D_IN / 4 + 255) / 256), 256>>>(X, bufA);

    // layer 1: [N,512] @ [512,1024] -> h
    gemm_mma<<<dim3(D_H / BN, N_ROWS / BM), 256, SMEM>>>(
        bufA, Bt1, b1, h, D_IN, D_H, 1);
    ln_convert<<<N_ROWS, 256>>>(h, g1, be1, bufA);

    // layer 2: [N,1024] @ [1024,1024] -> h (raw, pre-LN)
    gemm_mma<<<dim3(D_H / BN, N_ROWS / BM), 256, SMEM>>>(
        bufA, Bt2, b2, h, D_H, D_H, 1);

    // fused LN2 + per-group mean, then tiny fp32 GEMM (layer 3 via linearity)
    segmean_ln<<<NUM_GROUPS, 128>>>(h, ab, g2, be2, mean);
    minigemm<<<NUM_GROUPS / 8, 128>>>(mean, W3, b3, out);
}

// round 11
// speedup vs baseline: 1.1770x; 1.1178x over previous
#include <cuda_runtime.h>
#include <cuda_fp16.h>
#include <cstdint>
#include <cstddef>

#define N_ROWS     131072
#define D_IN       512
#define D_H        1024
#define D_OUT      128
#define NUM_GROUPS 1024
#define LN_EPS     1e-5f

// ---------------- scratch (device globals: allocation-free rule) -------------
__device__ __half g_bufA[(size_t)N_ROWS * 2048];      // layer inputs (fp16)
__device__ float  g_h  [(size_t)N_ROWS * D_H];        // fp32 hidden
__device__ float  g_mean[(size_t)NUM_GROUPS * D_H];   // 4 MB group means
__device__ __half g_Bt1[(size_t)D_H * D_IN];          // W1^T fp16 [1024, 512]
__device__ __half g_Bt2[(size_t)D_H * D_H];           // W2^T fp16 [1024, 1024]

// ======================= helpers ============================================
__device__ __forceinline__ uint32_t smem_u32(const void* p) {
    uint32_t a;
    asm("{ .reg .u64 t; cvta.to.shared.u64 t, %1; cvt.u32.u64 %0, t; }" : "=r"(a) : "l"(p));
    return a;
}
__device__ __forceinline__ uint32_t sw128(uint32_t b) { return b ^ ((b >> 3) & 0x70); }
__device__ __forceinline__ void cp_async16(uint32_t dst, const void* src) {
    asm volatile("cp.async.cg.shared.global [%0], [%1], 16;" :: "r"(dst), "l"(src) : "memory");
}
__device__ __forceinline__ void ldsm_x4(uint32_t* r, uint32_t addr) {
    asm volatile("ldmatrix.sync.aligned.m8n8.x4.shared.b16 {%0,%1,%2,%3}, [%4];"
                 : "=r"(r[0]), "=r"(r[1]), "=r"(r[2]), "=r"(r[3]) : "r"(addr));
}
__device__ __forceinline__ void mma_f16(float* c, const uint32_t* a, uint32_t b0, uint32_t b1) {
    asm volatile(
        "mma.sync.aligned.m16n8k16.row.col.f32.f16.f16.f32 "
        "{%0,%1,%2,%3}, {%4,%5,%6,%7}, {%8,%9}, {%0,%1,%2,%3};"
        : "+f"(c[0]), "+f"(c[1]), "+f"(c[2]), "+f"(c[3])
        : "r"(a[0]), "r"(a[1]), "r"(a[2]), "r"(a[3]), "r"(b0), "r"(b1));
}

// ======================= mma.sync fp16 GEMM =================================
// SPLIT=1: C = relu((A_hi + A_lo) @ Bt^T + bias), A = [M, 2K] (hi|lo), 2 stages
//          of [A_hi 16K | A_lo 16K | B 16K]; both terms into same accumulators.
// SPLIT=0: C = relu(A @ Bt^T + bias), A = [M, K] plain fp16, 3 stages of
//          [A 16K | B 16K] (2-deep lookahead).
// Both: Bt = [N, K] fp16, 128x128 CTA, 8 warps 4(m)x2(n), 128 regs, 2 CTA/SM.
#define BM 128
#define BN 128
#define BK 64
#define R_BYTES (BM * 128)                  // 16 KB per region

template <bool SPLIT>
__global__ void __launch_bounds__(256, 2)
gemm_mma(const __half* __restrict__ A, const __half* __restrict__ Bt,
         const float* __restrict__ bias, float* __restrict__ C,
         int K, int Ncols, int do_relu)
{
    constexpr int STG = SPLIT ? 2 : 3;
    constexpr int REG = SPLIT ? 3 : 2;
    constexpr int STAGE_BYTES = REG * R_BYTES;

    extern __shared__ __align__(1024) char smem[];
    const uint32_t sbase = smem_u32(smem);
    const int tid = threadIdx.x, lane = tid & 31, wid = tid >> 5;
    const int wm = wid & 3, wn = wid >> 2;                 // 4 x 2 warp grid
    const int m0 = blockIdx.y * BM, n0 = blockIdx.x * BN;
    const int lda = SPLIT ? 2 * K : K;
    const int NC = K / BK;

    auto fill = [&](int ci, int s) {
        const int kp = ci * BK;
        const uint32_t sAh = sbase + s * STAGE_BYTES;
        const uint32_t sB  = sAh + (REG - 1) * R_BYTES;
#pragma unroll
        for (int j = 0; j < 4; j++) {                 // A hi (or plain A)
            const int c = tid + j * 256;
            const int r = c >> 3, col = (c & 7) * 16;
            cp_async16(sAh + sw128(r * 128 + col),
                       (const char*)(A + (size_t)(m0 + r) * lda + kp) + col);
        }
        if constexpr (SPLIT) {
            const uint32_t sAl = sAh + R_BYTES;
#pragma unroll
            for (int j = 0; j < 4; j++) {             // A lo
                const int c = tid + j * 256;
                const int r = c >> 3, col = (c & 7) * 16;
                cp_async16(sAl + sw128(r * 128 + col),
                           (const char*)(A + (size_t)(m0 + r) * lda + K + kp) + col);
            }
        }
#pragma unroll
        for (int j = 0; j < 4; j++) {                 // B
            const int c = tid + j * 256;
            const int r = c >> 3, col = (c & 7) * 16;
            cp_async16(sB + sw128(r * 128 + col),
                       (const char*)(Bt + (size_t)(n0 + r) * K + kp) + col);
        }
        asm volatile("cp.async.commit_group;" ::: "memory");
    };

    float acc[2][8][4];
#pragma unroll
    for (int i = 0; i < 2; i++)
#pragma unroll
        for (int j = 0; j < 8; j++)
#pragma unroll
            for (int r = 0; r < 4; r++) acc[i][j][r] = 0.f;

    // prologue
    for (int j = 0; j < STG && j < NC; j++) fill(j, j);

    for (int i = 0; i < NC; i++) {
        const int s = i % STG;
        asm volatile("cp.async.wait_group %0;" :: "n"(STG - 1) : "memory");
        __syncthreads();
        const uint32_t sAh = sbase + s * STAGE_BYTES;
        const uint32_t sB  = sAh + (REG - 1) * R_BYTES;

#pragma unroll
        for (int k16 = 0; k16 < BK / 16; k16++) {
            const uint32_t kb = k16 * 32 + (lane >> 4) * 16;
            uint32_t b[4][4];
#pragma unroll
            for (int nt2 = 0; nt2 < 4; nt2++) {
                const int r = wn * 64 + nt2 * 16 + (lane & 15);
                ldsm_x4(b[nt2], sB + sw128(r * 128 + kb));
            }
            uint32_t a[2][4];
#pragma unroll
            for (int mt = 0; mt < 2; mt++) {          // hi term
                const int r = wm * 32 + mt * 16 + (lane & 15);
                ldsm_x4(a[mt], sAh + sw128(r * 128 + kb));
            }
#pragma unroll
            for (int mt = 0; mt < 2; mt++)
#pragma unroll
                for (int nt = 0; nt < 8; nt++)
                    mma_f16(acc[mt][nt], a[mt], b[nt >> 1][nt & 1], b[nt >> 1][2 + (nt & 1)]);
            if constexpr (SPLIT) {
                const uint32_t sAl = sAh + R_BYTES;
#pragma unroll
                for (int mt = 0; mt < 2; mt++) {      // lo term (reuse a regs)
                    const int r = wm * 32 + mt * 16 + (lane & 15);
                    ldsm_x4(a[mt], sAl + sw128(r * 128 + kb));
                }
#pragma unroll
                for (int mt = 0; mt < 2; mt++)
#pragma unroll
                    for (int nt = 0; nt < 8; nt++)
                        mma_f16(acc[mt][nt], a[mt], b[nt >> 1][nt & 1], b[nt >> 1][2 + (nt & 1)]);
            }
        }
        __syncthreads();
        if (i + STG < NC) fill(i + STG, s);
        else asm volatile("cp.async.commit_group;" ::: "memory");
    }

    // epilogue: bias + relu, fp32 stores
#pragma unroll
    for (int mt = 0; mt < 2; mt++) {
#pragma unroll
        for (int nt = 0; nt < 8; nt++) {
            const int col = n0 + wn * 64 + nt * 8 + (lane & 3) * 2;
            const float b0 = bias[col], b1 = bias[col + 1];
            const int r0 = m0 + wm * 32 + mt * 16 + (lane >> 2);
            float v0 = acc[mt][nt][0] + b0, v1 = acc[mt][nt][1] + b1;
            float v2 = acc[mt][nt][2] + b0, v3 = acc[mt][nt][3] + b1;
            if (do_relu) {
                v0 = fmaxf(v0, 0.f); v1 = fmaxf(v1, 0.f);
                v2 = fmaxf(v2, 0.f); v3 = fmaxf(v3, 0.f);
            }
            *(float2*)(C + (size_t)r0 * Ncols + col)       = make_float2(v0, v1);
            *(float2*)(C + (size_t)(r0 + 8) * Ncols + col) = make_float2(v2, v3);
        }
    }
}

// =================== operand prep kernels ===================================
__device__ __forceinline__ void split_f16(float x, __half& hi, __half& lo) {
    hi = __float2half_rn(x);
    lo = __float2half_rn(x - __half2float(hi));
}

// X [N, 512] f32 -> bufA [N, 512] plain fp16 (layer-1 error is W1-dominated)
__global__ void __launch_bounds__(256)
convertX(const float* __restrict__ X, __half* __restrict__ out)
{
    const size_t i4 = ((size_t)blockIdx.x * 256 + threadIdx.x) * 4;
    if (i4 >= (size_t)N_ROWS * D_IN) return;
    float4 v = *(const float4*)(X + i4);
    __half2 h01 = __halves2half2(__float2half_rn(v.x), __float2half_rn(v.y));
    __half2 h23 = __halves2half2(__float2half_rn(v.z), __float2half_rn(v.w));
    *(__half2*)(out + i4)     = h01;
    *(__half2*)(out + i4 + 2) = h23;
}

// W [K, Ncols] f32 -> Bt [Ncols, K] fp16 (rounded)
__global__ void __launch_bounds__(256)
convertW(const float* __restrict__ W, __half* __restrict__ Bt, int K, int Ncols)
{
    const size_t i = (size_t)blockIdx.x * 256 + threadIdx.x;
    if (i >= (size_t)K * Ncols) return;
    const int n = (int)(i % Ncols), k = (int)(i / Ncols);
    Bt[(size_t)n * K + k] = __float2half_rn(W[(size_t)k * Ncols + n]);
}

// -------- shared LN row-stat helper (256 threads, 1024 elems) ---------------
__device__ __forceinline__ void ln_stats(float4 v, float& mu, float& rs) {
    float s = v.x + v.y + v.z + v.w;
    float ss = v.x * v.x + v.y * v.y + v.z * v.z + v.w * v.w;
#pragma unroll
    for (int o = 16; o > 0; o >>= 1) {
        s  += __shfl_xor_sync(0xFFFFFFFFu, s,  o);
        ss += __shfl_xor_sync(0xFFFFFFFFu, ss, o);
    }
    __shared__ float ws[8], wss[8];
    const int t = threadIdx.x, w = t >> 5, l = t & 31;
    if (l == 0) { ws[w] = s; wss[w] = ss; }
    __syncthreads();
    if (w == 0) {
        s  = (l < 8) ? ws[l]  : 0.f;
        ss = (l < 8) ? wss[l] : 0.f;
#pragma unroll
        for (int o = 4; o > 0; o >>= 1) {
            s  += __shfl_xor_sync(0xFFFFFFFFu, s,  o);
            ss += __shfl_xor_sync(0xFFFFFFFFu, ss, o);
        }
        if (l == 0) { ws[0] = s; wss[0] = ss; }
    }
    __syncthreads();
    const float inv = 1.f / (float)D_H;
    mu = ws[0] * inv;
    const float var = fmaxf(wss[0] * inv - mu * mu, 0.f);
    rs = rsqrtf(var + LN_EPS);
}

// LayerNorm(h fp32 [N,1024]) -> bufA [N, 2048] fp16 (hi | lo)
__global__ void __launch_bounds__(256)
ln_convert(const float* __restrict__ H, const float* __restrict__ gamma,
           const float* __restrict__ beta, __half* __restrict__ out)
{
    const int row = blockIdx.x;
    const int t = threadIdx.x;
    float4 v = *(const float4*)(H + (size_t)row * D_H + t * 4);
    float mu, rs;
    ln_stats(v, mu, rs);

    float4 gv = *(const float4*)(gamma + t * 4);
    float4 bv = *(const float4*)(beta  + t * 4);
    float n0 = (v.x - mu) * rs * gv.x + bv.x;
    float n1 = (v.y - mu) * rs * gv.y + bv.y;
    float n2 = (v.z - mu) * rs * gv.z + bv.z;
    float n3 = (v.w - mu) * rs * gv.w + bv.w;
    __half h[4], lo[4];
    split_f16(n0, h[0], lo[0]); split_f16(n1, h[1], lo[1]);
    split_f16(n2, h[2], lo[2]); split_f16(n3, h[3], lo[3]);
    __half* oh = out + (size_t)row * 2048 + t * 4;
    __half* ol = oh + D_H;
    *(__half2*)(oh)     = __halves2half2(h[0], h[1]);
    *(__half2*)(oh + 2) = __halves2half2(h[2], h[3]);
    *(__half2*)(ol)     = __halves2half2(lo[0], lo[1]);
    *(__half2*)(ol + 2) = __halves2half2(lo[2], lo[3]);
}

// ======= fused LayerNorm + deterministic segment mean =======================
#define SEG_CAP 4096
__global__ void __launch_bounds__(128)
segmean_ln(const float* __restrict__ H, const int* __restrict__ batch,
           const float* __restrict__ gamma, const float* __restrict__ beta,
           float* __restrict__ mean)
{
    const int g = blockIdx.x;
    const int t = threadIdx.x;
    const int w = t >> 5, l = t & 31;

    __shared__ int s_cnt[128];
    __shared__ int s_idx[SEG_CAP];
    __shared__ int s_total;
    __shared__ float s_red[2][8];   // [parity][ws0..3 | wss0..3]

    int cnt = 0;
    for (int i = t; i < N_ROWS; i += 128)
        cnt += (batch[i] == g) ? 1 : 0;
    s_cnt[t] = cnt;
    __syncthreads();

    int off = 0;
    for (int u = 0; u < t; u++) off += s_cnt[u];
    if (t == 127) s_total = off + cnt;
    __syncthreads();
    const int total = s_total;

    int o = off;
    for (int i = t; i < N_ROWS; i += 128) {
        if (batch[i] == g) {
            if (o < SEG_CAP) s_idx[o] = i;
            o++;
        }
    }
    __syncthreads();

    float4 gv0 = *(const float4*)(gamma + t * 8);
    float4 gv1 = *(const float4*)(gamma + t * 8 + 4);
    float4 bv0 = *(const float4*)(beta  + t * 8);
    float4 bv1 = *(const float4*)(beta  + t * 8 + 4);

    float acc[8];
#pragma unroll
    for (int c = 0; c < 8; c++) acc[c] = 0.f;

    const int m = total < SEG_CAP ? total : SEG_CAP;
    const float invD = 1.f / (float)D_H;
    for (int j = 0; j < m; j++) {
        const float* row = H + (size_t)s_idx[j] * D_H + t * 8;
        float4 a = *(const float4*)(row);
        float4 b = *(const float4*)(row + 4);
        float s  = a.x + a.y + a.z + a.w + b.x + b.y + b.z + b.w;
        float ss = a.x * a.x + a.y * a.y + a.z * a.z + a.w * a.w
                 + b.x * b.x + b.y * b.y + b.z * b.z + b.w * b.w;
#pragma unroll
        for (int od = 16; od > 0; od >>= 1) {
            s  += __shfl_xor_sync(0xFFFFFFFFu, s,  od);
            ss += __shfl_xor_sync(0xFFFFFFFFu, ss, od);
        }
        const int p = j & 1;
        if (l == 0) { s_red[p][w] = s; s_red[p][4 + w] = ss; }
        __syncthreads();
        const float S  = s_red[p][0] + s_red[p][1] + s_red[p][2] + s_red[p][3];
        const float SS = s_red[p][4] + s_red[p][5] + s_red[p][6] + s_red[p][7];
        const float mu = S * invD;
        const float var = fmaxf(SS * invD - mu * mu, 0.f);
        const float rs = rsqrtf(var + LN_EPS);
        acc[0] += (a.x - mu) * rs * gv0.x + bv0.x;
        acc[1] += (a.y - mu) * rs * gv0.y + bv0.y;
        acc[2] += (a.z - mu) * rs * gv0.z + bv0.z;
        acc[3] += (a.w - mu) * rs * gv0.w + bv0.w;
        acc[4] += (b.x - mu) * rs * gv1.x + bv1.x;
        acc[5] += (b.y - mu) * rs * gv1.y + bv1.y;
        acc[6] += (b.z - mu) * rs * gv1.z + bv1.z;
        acc[7] += (b.w - mu) * rs * gv1.w + bv1.w;
    }

    const float inv = (total > 0) ? 1.f / (float)total : 0.f;
    float* dst = mean + (size_t)g * D_H + t * 8;
#pragma unroll
    for (int c = 0; c < 8; c += 4)
        *(float4*)(dst + c) = make_float4(acc[c] * inv, acc[c + 1] * inv,
                                          acc[c + 2] * inv, acc[c + 3] * inv);
}

// --------- tiny fp32 GEMM: out[G,128] = mean[G,1024] @ W3[1024,128] + b3 ----
__global__ void __launch_bounds__(128)
minigemm(const float* __restrict__ mean, const float* __restrict__ W3,
         const float* __restrict__ b3, float* __restrict__ out)
{
    __shared__ float sm[8][D_H];            // 8 group rows, 32 KB
    const int g0 = blockIdx.x * 8;
    const int t = threadIdx.x;              // output column

    for (int i = t; i < 8 * D_H; i += 128)
        sm[i >> 10][i & 1023] = mean[(size_t)(g0 + (i >> 10)) * D_H + (i & 1023)];
    __syncthreads();

    float acc[8];
#pragma unroll
    for (int r = 0; r < 8; r++) acc[r] = 0.f;
    for (int k = 0; k < D_H; k++) {
        const float w = W3[(size_t)k * D_OUT + t];
#pragma unroll
        for (int r = 0; r < 8; r++) acc[r] += sm[r][k] * w;
    }
    const float bb = b3[t];
#pragma unroll
    for (int r = 0; r < 8; r++)
        out[(size_t)(g0 + r) * D_OUT + t] = acc[r] + bb;
}

// ---------------- launch -----------------------------------------------------
extern "C" void kernel_launch(void* const* d_in, const int* in_sizes, int n_in,
                              void* d_out, int out_size)
{
    const float* X   = (const float*)d_in[0];
    const float* W1  = (const float*)d_in[1];
    const float* b1  = (const float*)d_in[2];
    const float* g1  = (const float*)d_in[3];
    const float* be1 = (const float*)d_in[4];
    const float* W2  = (const float*)d_in[5];
    const float* b2  = (const float*)d_in[6];
    const float* g2  = (const float*)d_in[7];
    const float* be2 = (const float*)d_in[8];
    const float* W3  = (const float*)d_in[9];
    const float* b3  = (const float*)d_in[10];
    const int*   ab  = (const int*)d_in[11];
    float* out = (float*)d_out;

    __half *bufA, *Bt1, *Bt2;
    float *h, *mean;
    cudaGetSymbolAddress((void**)&bufA, g_bufA);
    cudaGetSymbolAddress((void**)&h,    g_h);
    cudaGetSymbolAddress((void**)&mean, g_mean);
    cudaGetSymbolAddress((void**)&Bt1,  g_Bt1);
    cudaGetSymbolAddress((void**)&Bt2,  g_Bt2);

    const int SMEM = 6 * R_BYTES;   // 96 KB (2x3 or 3x2 regions x 16 KB)
    static bool attr_set = false;
    if (!attr_set) {
        cudaFuncSetAttribute(gemm_mma<false>, cudaFuncAttributeMaxDynamicSharedMemorySize, SMEM);
        cudaFuncSetAttribute(gemm_mma<true>,  cudaFuncAttributeMaxDynamicSharedMemorySize, SMEM);
        attr_set = true;
    }

    // operand prep
    convertW<<<(D_IN * D_H + 255) / 256, 256>>>(W1, Bt1, D_IN, D_H);
    convertW<<<(D_H * D_H + 255) / 256, 256>>>(W2, Bt2, D_H, D_H);
    convertX<<<(int)(((size_t)N_ROWS * D_IN / 4 + 255) / 256), 256>>>(X, bufA);

    // layer 1: plain fp16 [N,512] @ [512,1024] -> h
    gemm_mma<false><<<dim3(D_H / BN, N_ROWS / BM), 256, SMEM>>>(
        bufA, Bt1, b1, h, D_IN, D_H, 1);
    ln_convert<<<N_ROWS, 256>>>(h, g1, be1, bufA);

    // layer 2: split fp16 [N,1024] @ [1024,1024] -> h (raw, pre-LN)
    gemm_mma<true><<<dim3(D_H / BN, N_ROWS / BM), 256, SMEM>>>(
        bufA, Bt2, b2, h, D_H, D_H, 1);

    // fused LN2 + per-group mean, then tiny fp32 GEMM (layer 3 via linearity)
    segmean_ln<<<NUM_GROUPS, 128>>>(h, ab, g2, be2, mean);
    minigemm<<<NUM_GROUPS / 8, 128>>>(mean, W3, b3, out);
}

// round 12
// speedup vs baseline: 1.6742x; 1.4224x over previous
#include <cuda_runtime.h>
#include <cuda_fp16.h>
#include <cstdint>
#include <cstddef>

#define N_ROWS     131072
#define D_IN       512
#define D_H        1024
#define D_OUT      128
#define NUM_GROUPS 1024
#define LN_EPS     1e-5f

// ---------------- scratch (device globals: allocation-free rule) -------------
__device__ __half g_bufA[(size_t)N_ROWS * D_H];       // layer inputs (plain fp16)
__device__ float  g_h  [(size_t)N_ROWS * D_H];        // fp32 hidden
__device__ float  g_mean[(size_t)NUM_GROUPS * D_H];   // 4 MB group means
__device__ __half g_Bt1[(size_t)D_H * D_IN];          // W1^T fp16 [1024, 512]
__device__ __half g_Bt2[(size_t)D_H * D_H];           // W2^T fp16 [1024, 1024]

// ======================= helpers ============================================
__device__ __forceinline__ uint32_t smem_u32(const void* p) {
    uint32_t a;
    asm("{ .reg .u64 t; cvta.to.shared.u64 t, %1; cvt.u32.u64 %0, t; }" : "=r"(a) : "l"(p));
    return a;
}
__device__ __forceinline__ uint32_t sw128(uint32_t b) { return b ^ ((b >> 3) & 0x70); }
__device__ __forceinline__ void cp_async16(uint32_t dst, const void* src) {
    asm volatile("cp.async.cg.shared.global [%0], [%1], 16;" :: "r"(dst), "l"(src) : "memory");
}
__device__ __forceinline__ void ldsm_x4(uint32_t* r, uint32_t addr) {
    asm volatile("ldmatrix.sync.aligned.m8n8.x4.shared.b16 {%0,%1,%2,%3}, [%4];"
                 : "=r"(r[0]), "=r"(r[1]), "=r"(r[2]), "=r"(r[3]) : "r"(addr));
}
__device__ __forceinline__ void mma_f16(float* c, const uint32_t* a, uint32_t b0, uint32_t b1) {
    asm volatile(
        "mma.sync.aligned.m16n8k16.row.col.f32.f16.f16.f32 "
        "{%0,%1,%2,%3}, {%4,%5,%6,%7}, {%8,%9}, {%0,%1,%2,%3};"
        : "+f"(c[0]), "+f"(c[1]), "+f"(c[2]), "+f"(c[3])
        : "r"(a[0]), "r"(a[1]), "r"(a[2]), "r"(a[3]), "r"(b0), "r"(b1));
}

// ======================= mma.sync plain fp16 GEMM ===========================
// C[M, Ncols] = relu(A @ Bt^T + bias); A = [M, K] fp16, Bt = [N, K] fp16.
// 128x128 CTA, 8 warps 4(m)x2(n), 3 stages of [A 16K | B 16K], 128 regs,
// 2 CTAs/SM.
#define BM 128
#define BN 128
#define BK 64
#define STAGES 3
#define R_BYTES (BM * 128)                  // 16 KB per region
#define STAGE_BYTES (2 * R_BYTES)           // 32 KB

__global__ void __launch_bounds__(256, 2)
gemm_mma(const __half* __restrict__ A, const __half* __restrict__ Bt,
         const float* __restrict__ bias, float* __restrict__ C,
         int K, int Ncols, int do_relu)
{
    extern __shared__ __align__(1024) char smem[];
    const uint32_t sbase = smem_u32(smem);
    const int tid = threadIdx.x, lane = tid & 31, wid = tid >> 5;
    const int wm = wid & 3, wn = wid >> 2;                 // 4 x 2 warp grid
    const int m0 = blockIdx.y * BM, n0 = blockIdx.x * BN;
    const int NC = K / BK;

    auto fill = [&](int ci, int s) {
        const int kp = ci * BK;
        const uint32_t sA = sbase + s * STAGE_BYTES;
        const uint32_t sB = sA + R_BYTES;
#pragma unroll
        for (int j = 0; j < 4; j++) {
            const int c = tid + j * 256;
            const int r = c >> 3, col = (c & 7) * 16;
            cp_async16(sA + sw128(r * 128 + col),
                       (const char*)(A + (size_t)(m0 + r) * K + kp) + col);
        }
#pragma unroll
        for (int j = 0; j < 4; j++) {
            const int c = tid + j * 256;
            const int r = c >> 3, col = (c & 7) * 16;
            cp_async16(sB + sw128(r * 128 + col),
                       (const char*)(Bt + (size_t)(n0 + r) * K + kp) + col);
        }
        asm volatile("cp.async.commit_group;" ::: "memory");
    };

    float acc[2][8][4];
#pragma unroll
    for (int i = 0; i < 2; i++)
#pragma unroll
        for (int j = 0; j < 8; j++)
#pragma unroll
            for (int r = 0; r < 4; r++) acc[i][j][r] = 0.f;

    // prologue: fill all stages (2 chunks of lookahead)
    for (int j = 0; j < STAGES && j < NC; j++) fill(j, j);

    for (int i = 0; i < NC; i++) {
        const int s = i % STAGES;
        asm volatile("cp.async.wait_group %0;" :: "n"(STAGES - 1) : "memory");
        __syncthreads();
        const uint32_t sA = sbase + s * STAGE_BYTES;
        const uint32_t sB = sA + R_BYTES;

#pragma unroll
        for (int k16 = 0; k16 < BK / 16; k16++) {
            const uint32_t kb = k16 * 32 + (lane >> 4) * 16;
            uint32_t a[2][4];
#pragma unroll
            for (int mt = 0; mt < 2; mt++) {
                const int r = wm * 32 + mt * 16 + (lane & 15);
                ldsm_x4(a[mt], sA + sw128(r * 128 + kb));
            }
            uint32_t b[4][4];
#pragma unroll
            for (int nt2 = 0; nt2 < 4; nt2++) {
                const int r = wn * 64 + nt2 * 16 + (lane & 15);
                ldsm_x4(b[nt2], sB + sw128(r * 128 + kb));
            }
#pragma unroll
            for (int mt = 0; mt < 2; mt++)
#pragma unroll
                for (int nt = 0; nt < 8; nt++)
                    mma_f16(acc[mt][nt], a[mt], b[nt >> 1][nt & 1], b[nt >> 1][2 + (nt & 1)]);
        }
        __syncthreads();
        if (i + STAGES < NC) fill(i + STAGES, s);
        else asm volatile("cp.async.commit_group;" ::: "memory");
    }

    // epilogue: bias + relu, fp32 stores
#pragma unroll
    for (int mt = 0; mt < 2; mt++) {
#pragma unroll
        for (int nt = 0; nt < 8; nt++) {
            const int col = n0 + wn * 64 + nt * 8 + (lane & 3) * 2;
            const float b0 = bias[col], b1 = bias[col + 1];
            const int r0 = m0 + wm * 32 + mt * 16 + (lane >> 2);
            float v0 = acc[mt][nt][0] + b0, v1 = acc[mt][nt][1] + b1;
            float v2 = acc[mt][nt][2] + b0, v3 = acc[mt][nt][3] + b1;
            if (do_relu) {
                v0 = fmaxf(v0, 0.f); v1 = fmaxf(v1, 0.f);
                v2 = fmaxf(v2, 0.f); v3 = fmaxf(v3, 0.f);
            }
            *(float2*)(C + (size_t)r0 * Ncols + col)       = make_float2(v0, v1);
            *(float2*)(C + (size_t)(r0 + 8) * Ncols + col) = make_float2(v2, v3);
        }
    }
}

// =================== operand prep kernels ===================================
// X [N, 512] f32 -> bufA [N, 512] plain fp16
__global__ void __launch_bounds__(256)
convertX(const float* __restrict__ X, __half* __restrict__ out)
{
    const size_t i4 = ((size_t)blockIdx.x * 256 + threadIdx.x) * 4;
    if (i4 >= (size_t)N_ROWS * D_IN) return;
    float4 v = *(const float4*)(X + i4);
    *(__half2*)(out + i4)     = __halves2half2(__float2half_rn(v.x), __float2half_rn(v.y));
    *(__half2*)(out + i4 + 2) = __halves2half2(__float2half_rn(v.z), __float2half_rn(v.w));
}

// W [K, Ncols] f32 -> Bt [Ncols, K] fp16 (rounded)
__global__ void __launch_bounds__(256)
convertW(const float* __restrict__ W, __half* __restrict__ Bt, int K, int Ncols)
{
    const size_t i = (size_t)blockIdx.x * 256 + threadIdx.x;
    if (i >= (size_t)K * Ncols) return;
    const int n = (int)(i % Ncols), k = (int)(i / Ncols);
    Bt[(size_t)n * K + k] = __float2half_rn(W[(size_t)k * Ncols + n]);
}

// -------- shared LN row-stat helper (256 threads, 1024 elems) ---------------
__device__ __forceinline__ void ln_stats(float4 v, float& mu, float& rs) {
    float s = v.x + v.y + v.z + v.w;
    float ss = v.x * v.x + v.y * v.y + v.z * v.z + v.w * v.w;
#pragma unroll
    for (int o = 16; o > 0; o >>= 1) {
        s  += __shfl_xor_sync(0xFFFFFFFFu, s,  o);
        ss += __shfl_xor_sync(0xFFFFFFFFu, ss, o);
    }
    __shared__ float ws[8], wss[8];
    const int t = threadIdx.x, w = t >> 5, l = t & 31;
    if (l == 0) { ws[w] = s; wss[w] = ss; }
    __syncthreads();
    if (w == 0) {
        s  = (l < 8) ? ws[l]  : 0.f;
        ss = (l < 8) ? wss[l] : 0.f;
#pragma unroll
        for (int o = 4; o > 0; o >>= 1) {
            s  += __shfl_xor_sync(0xFFFFFFFFu, s,  o);
            ss += __shfl_xor_sync(0xFFFFFFFFu, ss, o);
        }
        if (l == 0) { ws[0] = s; wss[0] = ss; }
    }
    __syncthreads();
    const float inv = 1.f / (float)D_H;
    mu = ws[0] * inv;
    const float var = fmaxf(wss[0] * inv - mu * mu, 0.f);
    rs = rsqrtf(var + LN_EPS);
}

// LayerNorm(h fp32 [N,1024]) -> bufA [N, 1024] plain fp16
__global__ void __launch_bounds__(256)
ln_convert(const float* __restrict__ H, const float* __restrict__ gamma,
           const float* __restrict__ beta, __half* __restrict__ out)
{
    const int row = blockIdx.x;
    const int t = threadIdx.x;
    float4 v = *(const float4*)(H + (size_t)row * D_H + t * 4);
    float mu, rs;
    ln_stats(v, mu, rs);

    float4 gv = *(const float4*)(gamma + t * 4);
    float4 bv = *(const float4*)(beta  + t * 4);
    float n0 = (v.x - mu) * rs * gv.x + bv.x;
    float n1 = (v.y - mu) * rs * gv.y + bv.y;
    float n2 = (v.z - mu) * rs * gv.z + bv.z;
    float n3 = (v.w - mu) * rs * gv.w + bv.w;
    __half* oh = out + (size_t)row * D_H + t * 4;
    *(__half2*)(oh)     = __halves2half2(__float2half_rn(n0), __float2half_rn(n1));
    *(__half2*)(oh + 2) = __halves2half2(__float2half_rn(n2), __float2half_rn(n3));
}

// ======= fused LayerNorm + deterministic segment mean =======================
#define SEG_CAP 4096
__global__ void __launch_bounds__(128)
segmean_ln(const float* __restrict__ H, const int* __restrict__ batch,
           const float* __restrict__ gamma, const float* __restrict__ beta,
           float* __restrict__ mean)
{
    const int g = blockIdx.x;
    const int t = threadIdx.x;
    const int w = t >> 5, l = t & 31;

    __shared__ int s_cnt[128];
    __shared__ int s_idx[SEG_CAP];
    __shared__ int s_total;
    __shared__ float s_red[2][8];   // [parity][ws0..3 | wss0..3]

    int cnt = 0;
    for (int i = t; i < N_ROWS; i += 128)
        cnt += (batch[i] == g) ? 1 : 0;
    s_cnt[t] = cnt;
    __syncthreads();

    int off = 0;
    for (int u = 0; u < t; u++) off += s_cnt[u];
    if (t == 127) s_total = off + cnt;
    __syncthreads();
    const int total = s_total;

    int o = off;
    for (int i = t; i < N_ROWS; i += 128) {
        if (batch[i] == g) {
            if (o < SEG_CAP) s_idx[o] = i;
            o++;
        }
    }
    __syncthreads();

    float4 gv0 = *(const float4*)(gamma + t * 8);
    float4 gv1 = *(const float4*)(gamma + t * 8 + 4);
    float4 bv0 = *(const float4*)(beta  + t * 8);
    float4 bv1 = *(const float4*)(beta  + t * 8 + 4);

    float acc[8];
#pragma unroll
    for (int c = 0; c < 8; c++) acc[c] = 0.f;

    const int m = total < SEG_CAP ? total : SEG_CAP;
    const float invD = 1.f / (float)D_H;
    for (int j = 0; j < m; j++) {
        const float* row = H + (size_t)s_idx[j] * D_H + t * 8;
        float4 a = *(const float4*)(row);
        float4 b = *(const float4*)(row + 4);
        float s  = a.x + a.y + a.z + a.w + b.x + b.y + b.z + b.w;
        float ss = a.x * a.x + a.y * a.y + a.z * a.z + a.w * a.w
                 + b.x * b.x + b.y * b.y + b.z * b.z + b.w * b.w;
#pragma unroll
        for (int od = 16; od > 0; od >>= 1) {
            s  += __shfl_xor_sync(0xFFFFFFFFu, s,  od);
            ss += __shfl_xor_sync(0xFFFFFFFFu, ss, od);
        }
        const int p = j & 1;
        if (l == 0) { s_red[p][w] = s; s_red[p][4 + w] = ss; }
        __syncthreads();
        const float S  = s_red[p][0] + s_red[p][1] + s_red[p][2] + s_red[p][3];
        const float SS = s_red[p][4] + s_red[p][5] + s_red[p][6] + s_red[p][7];
        const float mu = S * invD;
        const float var = fmaxf(SS * invD - mu * mu, 0.f);
        const float rs = rsqrtf(var + LN_EPS);
        acc[0] += (a.x - mu) * rs * gv0.x + bv0.x;
        acc[1] += (a.y - mu) * rs * gv0.y + bv0.y;
        acc[2] += (a.z - mu) * rs * gv0.z + bv0.z;
        acc[3] += (a.w - mu) * rs * gv0.w + bv0.w;
        acc[4] += (b.x - mu) * rs * gv1.x + bv1.x;
        acc[5] += (b.y - mu) * rs * gv1.y + bv1.y;
        acc[6] += (b.z - mu) * rs * gv1.z + bv1.z;
        acc[7] += (b.w - mu) * rs * gv1.w + bv1.w;
    }

    const float inv = (total > 0) ? 1.f / (float)total : 0.f;
    float* dst = mean + (size_t)g * D_H + t * 8;
#pragma unroll
    for (int c = 0; c < 8; c += 4)
        *(float4*)(dst + c) = make_float4(acc[c] * inv, acc[c + 1] * inv,
                                          acc[c + 2] * inv, acc[c + 3] * inv);
}

// --------- tiny fp32 GEMM: out[G,128] = mean[G,1024] @ W3[1024,128] + b3 ----
__global__ void __launch_bounds__(128)
minigemm(const float* __restrict__ mean, const float* __restrict__ W3,
         const float* __restrict__ b3, float* __restrict__ out)
{
    __shared__ float sm[8][D_H];            // 8 group rows, 32 KB
    const int g0 = blockIdx.x * 8;
    const int t = threadIdx.x;              // output column

    for (int i = t; i < 8 * D_H; i += 128)
        sm[i >> 10][i & 1023] = mean[(size_t)(g0 + (i >> 10)) * D_H + (i & 1023)];
    __syncthreads();

    float acc[8];
#pragma unroll
    for (int r = 0; r < 8; r++) acc[r] = 0.f;
    for (int k = 0; k < D_H; k++) {
        const float w = W3[(size_t)k * D_OUT + t];
#pragma unroll
        for (int r = 0; r < 8; r++) acc[r] += sm[r][k] * w;
    }
    const float bb = b3[t];
#pragma unroll
    for (int r = 0; r < 8; r++)
        out[(size_t)(g0 + r) * D_OUT + t] = acc[r] + bb;
}

// ---------------- launch -----------------------------------------------------
extern "C" void kernel_launch(void* const* d_in, const int* in_sizes, int n_in,
                              void* d_out, int out_size)
{
    const float* X   = (const float*)d_in[0];
    const float* W1  = (const float*)d_in[1];
    const float* b1  = (const float*)d_in[2];
    const float* g1  = (const float*)d_in[3];
    const float* be1 = (const float*)d_in[4];
    const float* W2  = (const float*)d_in[5];
    const float* b2  = (const float*)d_in[6];
    const float* g2  = (const float*)d_in[7];
    const float* be2 = (const float*)d_in[8];
    const float* W3  = (const float*)d_in[9];
    const float* b3  = (const float*)d_in[10];
    const int*   ab  = (const int*)d_in[11];
    float* out = (float*)d_out;

    __half *bufA, *Bt1, *Bt2;
    float *h, *mean;
    cudaGetSymbolAddress((void**)&bufA, g_bufA);
    cudaGetSymbolAddress((void**)&h,    g_h);
    cudaGetSymbolAddress((void**)&mean, g_mean);
    cudaGetSymbolAddress((void**)&Bt1,  g_Bt1);
    cudaGetSymbolAddress((void**)&Bt2,  g_Bt2);

    const int SMEM = STAGES * STAGE_BYTES;   // 96 KB
    static bool attr_set = false;
    if (!attr_set) {
        cudaFuncSetAttribute(gemm_mma, cudaFuncAttributeMaxDynamicSharedMemorySize, SMEM);
        attr_set = true;
    }

    // operand prep
    convertW<<<(D_IN * D_H + 255) / 256, 256>>>(W1, Bt1, D_IN, D_H);
    convertW<<<(D_H * D_H + 255) / 256, 256>>>(W2, Bt2, D_H, D_H);
    convertX<<<(int)(((size_t)N_ROWS * D_IN / 4 + 255) / 256), 256>>>(X, bufA);

    // layer 1: plain fp16 [N,512] @ [512,1024] -> h
    gemm_mma<<<dim3(D_H / BN, N_ROWS / BM), 256, SMEM>>>(
        bufA, Bt1, b1, h, D_IN, D_H, 1);
    ln_convert<<<N_ROWS, 256>>>(h, g1, be1, bufA);

    // layer 2: plain fp16 [N,1024] @ [1024,1024] -> h (raw, pre-LN)
    gemm_mma<<<dim3(D_H / BN, N_ROWS / BM), 256, SMEM>>>(
        bufA, Bt2, b2, h, D_H, D_H, 1);

    // fused LN2 + per-group mean, then tiny fp32 GEMM (layer 3 via linearity)
    segmean_ln<<<NUM_GROUPS, 128>>>(h, ab, g2, be2, mean);
    minigemm<<<NUM_GROUPS / 8, 128>>>(mean, W3, b3, out);
}